// round 4
// baseline (speedup 1.0000x reference)
#include <cuda_runtime.h>
#include <math.h>

#define BATCH 8
#define CIN   128
#define CD    64
#define Hh    128
#define Ww    128
#define HW    (Hh*Ww)
#define NE    4
#define NBLK  64          // prefuse blocks per batch image (HW/256)

// ---- scratch (device globals; no allocation allowed) ----
__device__ float g_y[(size_t)BATCH*CD*HW];      // pre_fuse output, 33.5 MB
__device__ float g_pmax[BATCH*CD*NBLK];         // per-block pooling partials
__device__ float g_psum[BATCH*CD*NBLK];
__device__ float g_cof[BATCH*NE];               // gating coefficients (0 for unselected)

// ============================================================
// Kernel A: pre_fuse 1x1 conv + fused pooling partials.
// y[b,o,p] = sum_c x[b,c,p]*W[o,c] + bias[o]
// 256 threads = 8 warps; warp `to` owns channels to*8..to*8+7,
// lane tp owns 8 pixels: {pbase+tp*4..+3} and {pbase+128+tp*4..+3}.
// Register tile 8 ch x 8 px -> 64 FFMA per K step, 4 LDS.128.
// ============================================================
#define KC 16
__global__ void __launch_bounds__(256) prefuse_kernel(
        const float* __restrict__ x,
        const float* __restrict__ pre_w,
        const float* __restrict__ pre_b) {
    __shared__ float4 w_s4[CIN*16];   // transposed [c][o/4], 32 KB
    __shared__ float4 x_s4[KC*64];    // K-chunk [cc][px/4],  16 KB

    const int b     = blockIdx.y;
    const int blkx  = blockIdx.x;          // 0..63
    const int pbase = blkx * 256;
    const int tid   = threadIdx.x;
    const int to    = tid >> 5;             // warp id = channel group
    const int tp    = tid & 31;             // lane = pixel group

    // load W transposed (one-time): w_s[c*CD + o] = pre_w[o*CIN + c]
    {
        float* w_s = reinterpret_cast<float*>(w_s4);
        for (int i = tid; i < CIN*CD; i += 256) {
            int o = i / CIN, c = i % CIN;
            w_s[c*CD + o] = pre_w[i];
        }
    }

    float acc[8][8];
    #pragma unroll
    for (int j = 0; j < 8; j++)
        #pragma unroll
        for (int p = 0; p < 8; p++) acc[j][p] = 0.f;

    const float* xb = x + (size_t)b*CIN*HW + pbase;

    for (int c0 = 0; c0 < CIN; c0 += KC) {
        __syncthreads();
        // fill KC x 256 chunk: 1024 float4 slots, 4 per thread
        #pragma unroll
        for (int r = 0; r < 4; r++) {
            int s    = tid + r*256;
            int row  = s >> 6;            // 0..15
            int col4 = s & 63;            // 0..63
            x_s4[s] = reinterpret_cast<const float4*>(xb + (size_t)(c0+row)*HW)[col4];
        }
        __syncthreads();

        #pragma unroll 4
        for (int cc = 0; cc < KC; cc++) {
            float4 xa = x_s4[cc*64 + tp];        // pixels tp*4..+3
            float4 xc = x_s4[cc*64 + 32 + tp];   // pixels 128+tp*4..+3
            float4 w0 = w_s4[(c0+cc)*16 + to*2];     // channels to*8..+3
            float4 w1 = w_s4[(c0+cc)*16 + to*2 + 1]; // channels to*8+4..+7
            float wv[8] = {w0.x,w0.y,w0.z,w0.w, w1.x,w1.y,w1.z,w1.w};
            float xv[8] = {xa.x,xa.y,xa.z,xa.w, xc.x,xc.y,xc.z,xc.w};
            #pragma unroll
            for (int j = 0; j < 8; j++)
                #pragma unroll
                for (int p = 0; p < 8; p++)
                    acc[j][p] += wv[j] * xv[p];
        }
    }

    // epilogue: bias, store, fused pooling partials
    float* yb = g_y + (size_t)b*CD*HW + pbase;
    #pragma unroll
    for (int j = 0; j < 8; j++) {
        int o = to*8 + j;
        float bias = pre_b[o];
        float v[8];
        float vmax = -3.4e38f, vsum = 0.f;
        #pragma unroll
        for (int p = 0; p < 8; p++) {
            v[p] = acc[j][p] + bias;
            vmax = fmaxf(vmax, v[p]);
            vsum += v[p];
        }
        float4 va = make_float4(v[0],v[1],v[2],v[3]);
        float4 vc = make_float4(v[4],v[5],v[6],v[7]);
        reinterpret_cast<float4*>(&yb[(size_t)o*HW])[tp]      = va;
        reinterpret_cast<float4*>(&yb[(size_t)o*HW + 128])[tp] = vc;
        // warp reduction (all lanes share channel o)
        #pragma unroll
        for (int off = 16; off; off >>= 1) {
            vmax = fmaxf(vmax, __shfl_xor_sync(0xffffffffu, vmax, off));
            vsum += __shfl_xor_sync(0xffffffffu, vsum, off);
        }
        if (tp == 0) {
            g_pmax[(b*CD + o)*NBLK + blkx] = vmax;
            g_psum[(b*CD + o)*NBLK + blkx] = vsum;
        }
    }
}

// ============================================================
// Kernel C: pooling finalize + gate network + top-2 softmax.
// 512 threads: phase 1 reduces partials (1 thread per (b,o)),
// phase 2: threads 0..7 run the gate math.
// ============================================================
__global__ void gate_kernel(const float* __restrict__ gw0, const float* __restrict__ gb0,
                            const float* __restrict__ gw1, const float* __restrict__ gb1) {
    __shared__ float pooled_s[BATCH*CD];
    const int tid = threadIdx.x;

    // phase 1: reduce NBLK partials for each of 512 (b,o)
    {
        const float* pm = g_pmax + tid*NBLK;
        const float* ps = g_psum + tid*NBLK;
        float m = -3.4e38f, s = 0.f;
        #pragma unroll 8
        for (int k = 0; k < NBLK; k++) { m = fmaxf(m, pm[k]); s += ps[k]; }
        pooled_s[tid] = m + s * (1.0f/(float)HW);
    }
    __syncthreads();

    // phase 2: gate for each batch element
    int b = tid;
    if (b >= BATCH) return;
    const float* pl = pooled_s + b*CD;

    float logits[NE], noise[NE];
    #pragma unroll
    for (int e = 0; e < NE; e++) {
        float a0 = gb0[e], a1 = gb1[e];
        for (int c = 0; c < CD; c++) {
            float pv = pl[c];
            a0 += pv * gw0[e*CD + c];
            a1 += pv * gw1[e*CD + c];
        }
        logits[e] = (a1 > 0.f) ? a1 : 0.2f*a1;                 // leaky_relu 0.2
        noise[e]  = (a0 > 20.f) ? a0 : log1pf(expf(a0));       // softplus
    }
    float mean = 0.f;
    #pragma unroll
    for (int e = 0; e < NE; e++) mean += noise[e];
    mean *= 0.25f;
    float var = 0.f;
    #pragma unroll
    for (int e = 0; e < NE; e++) { float d = noise[e]-mean; var += d*d; }
    float stdv = sqrtf(var * (1.0f/3.0f));                     // ddof=1, n=4
    float scores[NE];
    #pragma unroll
    for (int e = 0; e < NE; e++) scores[e] = logits[e] + (noise[e]-mean)/stdv;

    int i1 = 0;
    #pragma unroll
    for (int e = 1; e < NE; e++) if (scores[e] > scores[i1]) i1 = e;
    int i2 = -1;
    #pragma unroll
    for (int e = 0; e < NE; e++) {
        if (e == i1) continue;
        if (i2 < 0 || scores[e] > scores[i2]) i2 = e;
    }
    float m  = fmaxf(logits[i1], logits[i2]);
    float e1 = expf(logits[i1]-m), e2 = expf(logits[i2]-m);
    float inv = 1.0f/(e1+e2);
    #pragma unroll
    for (int e = 0; e < NE; e++) g_cof[b*NE+e] = 0.f;
    g_cof[b*NE+i1] = e1*inv;
    g_cof[b*NE+i2] = e2*inv;
}

// ============================================================
// Kernel D: fused top-2 experts — column-stationary.
// Block = 256 threads = 128 columns x 2 row-groups; register
// sliding windows; GELU via erff (inputs tiny -> fast poly path).
// ============================================================
#define TH 16
#define YS_W 132
__device__ __forceinline__ float gelu_exact(float a) {
    return a * (0.5f + 0.5f * erff(a * 0.70710678118654752f));
}
__global__ void expert_kernel(const float* __restrict__ exp_w1, const float* __restrict__ exp_b1,
                              const float* __restrict__ exp_w2, const float* __restrict__ exp_b2,
                              float* __restrict__ out) {
    __shared__ float ys[20*YS_W];
    __shared__ float hs[18*YS_W];

    const int tile = blockIdx.x;          // 0..7
    const int c    = blockIdx.y;          // 0..63
    const int b    = blockIdx.z;          // 0..7
    const int r0   = tile * TH;
    const int tid  = threadIdx.x;
    const int tp   = tid & 127;           // column 0..127
    const int rg   = tid >> 7;            // row-group 0/1

    float cof[NE];
    #pragma unroll
    for (int e = 0; e < NE; e++) cof[e] = g_cof[b*NE + e];

    // ---- load y tile with halo: rows 0..19 (global r0-2 .. r0+17) ----
    const float* yb = g_y + ((size_t)b*CD + c)*HW;
    #pragma unroll
    for (int k = 0; k < 10; k++) {
        int r  = rg*10 + k;
        int gr = r0 - 2 + r;
        float v = (gr >= 0 && gr < Hh) ? yb[gr*Ww + tp] : 0.f;
        ys[r*YS_W + tp + 2] = v;
        if (tp < 2)    ys[r*YS_W + tp]     = 0.f;   // cols -2,-1
        if (tp >= 126) ys[r*YS_W + tp + 4] = 0.f;   // cols 128,129
    }
    if (tid < 18) {
        hs[tid*YS_W + 1]   = 0.f;
        hs[tid*YS_W + 130] = 0.f;
    }
    __syncthreads();

    float oacc[8];
    #pragma unroll
    for (int k = 0; k < 8; k++) oacc[k] = 0.f;

    for (int e = 0; e < NE; e++) {
        float ce = cof[e];
        if (ce == 0.f) continue;    // uniform branch

        const float* pw1 = exp_w1 + (size_t)(e*CD + c)*9;
        const float* pw2 = exp_w2 + (size_t)(e*CD + c)*9;
        float w1[9], w2[9];
        #pragma unroll
        for (int j = 0; j < 9; j++) { w1[j] = pw1[j]; w2[j] = pw2[j]; }
        const float bb1 = exp_b1[e*CD + c];
        const float bb2 = exp_b2[e*CD + c];

        // ---- conv1 + GELU -> hs, rows rg*9 .. rg*9+8, fixed col tp+2 ----
        {
            const int rs = rg * 9;
            const float* y0 = &ys[rs*YS_W + tp + 1];
            float a0 = y0[0],        a1 = y0[1],        a2 = y0[2];
            float d0 = y0[YS_W],     d1 = y0[YS_W+1],   d2 = y0[YS_W+2];
            #pragma unroll
            for (int k = 0; k < 9; k++) {
                const float* yr = y0 + (k+2)*YS_W;
                float f0 = yr[0], f1 = yr[1], f2 = yr[2];
                float a = bb1;
                a += a0*w1[0] + a1*w1[1] + a2*w1[2];
                a += d0*w1[3] + d1*w1[4] + d2*w1[5];
                a += f0*w1[6] + f1*w1[7] + f2*w1[8];
                int gr = r0 - 1 + rs + k;
                float hval = (gr >= 0 && gr < Hh) ? gelu_exact(a) : 0.f;
                hs[(rs+k)*YS_W + tp + 2] = hval;
                a0 = d0; a1 = d1; a2 = d2;
                d0 = f0; d1 = f1; d2 = f2;
            }
        }
        __syncthreads();

        // ---- conv2 -> oacc, rows rg*8 .. rg*8+7, fixed col tp ----
        {
            const int rs = rg * 8;
            const float* h0 = &hs[rs*YS_W + tp + 1];
            float a0 = h0[0],        a1 = h0[1],        a2 = h0[2];
            float d0 = h0[YS_W],     d1 = h0[YS_W+1],   d2 = h0[YS_W+2];
            #pragma unroll
            for (int k = 0; k < 8; k++) {
                const float* hr = h0 + (k+2)*YS_W;
                float f0 = hr[0], f1 = hr[1], f2 = hr[2];
                float a = bb2;
                a += a0*w2[0] + a1*w2[1] + a2*w2[2];
                a += d0*w2[3] + d1*w2[4] + d2*w2[5];
                a += f0*w2[6] + f1*w2[7] + f2*w2[8];
                oacc[k] += ce * a;
                a0 = d0; a1 = d1; a2 = d2;
                d0 = f0; d1 = f1; d2 = f2;
            }
        }
        __syncthreads();   // hs reused by next expert
    }

    float* ob = out + ((size_t)b*CD + c)*HW + (r0 + rg*8)*Ww + tp;
    #pragma unroll
    for (int k = 0; k < 8; k++) ob[k*Ww] = oacc[k];
}

// ============================================================
extern "C" void kernel_launch(void* const* d_in, const int* in_sizes, int n_in,
                              void* d_out, int out_size) {
    const float* x      = (const float*)d_in[0];
    const float* pre_w  = (const float*)d_in[1];
    const float* pre_b  = (const float*)d_in[2];
    const float* gw0    = (const float*)d_in[3];
    const float* gb0    = (const float*)d_in[4];
    const float* gw1    = (const float*)d_in[5];
    const float* gb1    = (const float*)d_in[6];
    const float* ew1    = (const float*)d_in[7];
    const float* eb1    = (const float*)d_in[8];
    const float* ew2    = (const float*)d_in[9];
    const float* eb2    = (const float*)d_in[10];
    float* out = (float*)d_out;

    dim3 gA(NBLK, BATCH);
    prefuse_kernel<<<gA, 256>>>(x, pre_w, pre_b);
    gate_kernel<<<1, 512>>>(gw0, gb0, gw1, gb1);
    dim3 gD(Hh/TH, CD, BATCH);
    expert_kernel<<<gD, 256>>>(ew1, eb1, ew2, eb2, out);
}